// round 5
// baseline (speedup 1.0000x reference)
#include <cuda_runtime.h>
#include <cuda_bf16.h>
#include <math.h>
#include <stdint.h>

// Problem constants
#define NB   8192
#define NC   200
#define NK   16
#define ND   512
#define NCK  3200
#define K2   1024          // 2*ND concatenated GEMM K
#define D_LOG_2PI 940.9930579935848f

// GEMM tiling
#define BM 256
#define BN 128
#define BK 64              // bf16 per stage row (128 bytes, SW128 atom)
#define NSTEPS (K2/BK)     // 16
#define NTHR 512

// SMEM layout (dynamic):
//  [0:512)    bias_sm (128 floats)
//  [512 + s*STAGE): stage s: Ah(32K) Al(32K) Bh(16K) Bl(16K)
//  epilogue reuses [512, ...) as C staging (256 x 136 floats)
#define STAGE_BYTES 98304
#define SMEM_TOTAL  (512 + 2 * STAGE_BYTES)
#define CPAD 136

// ---------------- scratch (device globals) ----------------
__device__ __nv_bfloat16 g_Ah[NB * K2];
__device__ __nv_bfloat16 g_Al[NB * K2];
__device__ __nv_bfloat16 g_Bh[NCK * K2];
__device__ __nv_bfloat16 g_Bl[NCK * K2];
__device__ float g_bias[NCK];
__device__ float g_logw[NCK];
__device__ float g_logp[NC];
__device__ float g_cls[NB * NC];

// ---------------- helpers ----------------
__device__ __forceinline__ uint32_t smem_u32(const void* p) {
    uint32_t a;
    asm("{ .reg .u64 t; cvta.to.shared.u64 t, %1; cvt.u32.u64 %0, t; }" : "=r"(a) : "l"(p));
    return a;
}
__device__ __forceinline__ uint32_t swz(uint32_t o) {   // SW128, 128B rows
    return o ^ (((o >> 7) & 7) << 4);
}
__device__ __forceinline__ void cp16(uint32_t saddr, const void* gaddr) {
    asm volatile("cp.async.cg.shared.global [%0], [%1], 16;" :: "r"(saddr), "l"(gaddr));
}
__device__ __forceinline__ void ldsm4(uint32_t* r, uint32_t addr) {
    asm volatile("ldmatrix.sync.aligned.m8n8.x4.shared.b16 {%0,%1,%2,%3}, [%4];"
        : "=r"(r[0]), "=r"(r[1]), "=r"(r[2]), "=r"(r[3]) : "r"(addr));
}
// direct-operand MMA: no temp arrays
__device__ __forceinline__ void mma4(float* c, const uint32_t* a, uint32_t b0, uint32_t b1) {
    asm("mma.sync.aligned.m16n8k16.row.col.f32.bf16.bf16.f32 "
        "{%0,%1,%2,%3}, {%4,%5,%6,%7}, {%8,%9}, {%0,%1,%2,%3};"
        : "+f"(c[0]), "+f"(c[1]), "+f"(c[2]), "+f"(c[3])
        : "r"(a[0]), "r"(a[1]), "r"(a[2]), "r"(a[3]), "r"(b0), "r"(b1));
}

// ---------------- prep kernels ----------------
__global__ void prep_x_kernel(const float* __restrict__ x) {
    int i = blockIdx.x * blockDim.x + threadIdx.x;
    if (i < NB * ND) {
        int b = i >> 9, d = i & 511;
        float v = x[i];
        float a = v * v;
        __nv_bfloat16 h = __float2bfloat16(a);
        g_Ah[b * K2 + d] = h;
        g_Al[b * K2 + d] = __float2bfloat16(a - __bfloat162float(h));
        __nv_bfloat16 h2 = __float2bfloat16(v);
        g_Ah[b * K2 + ND + d] = h2;
        g_Al[b * K2 + ND + d] = __float2bfloat16(v - __bfloat162float(h2));
    }
}

__global__ void prep_wp_kernel(const float* __restrict__ weights,
                               const float* __restrict__ priors) {
    __shared__ float sh[256];
    int t = threadIdx.x;
    if (t < NC) {
        float wv[NK];
        float m = -1e30f;
        #pragma unroll
        for (int k = 0; k < NK; k++) { wv[k] = weights[t * NK + k]; m = fmaxf(m, wv[k]); }
        float s = 0.f;
        #pragma unroll
        for (int k = 0; k < NK; k++) s += expf(wv[k] - m);
        float inv_s = 1.f / s;
        #pragma unroll
        for (int k = 0; k < NK; k++)
            g_logw[t * NK + k] = logf(expf(wv[k] - m) * inv_s + 1e-6f);
    }
    float pv = (t < NC) ? priors[t] : -1e30f;
    sh[t] = pv;
    __syncthreads();
    for (int s = 128; s > 0; s >>= 1) { if (t < s) sh[t] = fmaxf(sh[t], sh[t + s]); __syncthreads(); }
    float M = sh[0];
    __syncthreads();
    float e = (t < NC) ? expf(pv - M) : 0.f;
    sh[t] = e;
    __syncthreads();
    for (int s = 128; s > 0; s >>= 1) { if (t < s) sh[t] += sh[t + s]; __syncthreads(); }
    float S = sh[0];
    if (t < NC) g_logp[t] = logf(e / S + 1e-6f);
}

__global__ void prep_comp_kernel(const float* __restrict__ means,
                                 const float* __restrict__ bw) {
    int j = blockIdx.x;
    int t = threadIdx.x;   // 128
    float ld = 0.f, cj = 0.f;
    #pragma unroll
    for (int d = t; d < ND; d += 128) {
        float bv = bw[j * ND + d];
        bv = fminf(fmaxf(bv, 1e-6f), 1000.f);
        float inv = 1.0f / bv;
        float mu  = means[j * ND + d];
        float m2  = -2.0f * mu * inv;
        __nv_bfloat16 h = __float2bfloat16(inv);
        g_Bh[j * K2 + d] = h;
        g_Bl[j * K2 + d] = __float2bfloat16(inv - __bfloat162float(h));
        __nv_bfloat16 h2 = __float2bfloat16(m2);
        g_Bh[j * K2 + ND + d] = h2;
        g_Bl[j * K2 + ND + d] = __float2bfloat16(m2 - __bfloat162float(h2));
        ld += logf(bv);
        cj += mu * mu * inv;
    }
    __shared__ float shd[128], shc[128];
    shd[t] = ld; shc[t] = cj;
    __syncthreads();
    for (int s = 64; s > 0; s >>= 1) {
        if (t < s) { shd[t] += shd[t + s]; shc[t] += shc[t + s]; }
        __syncthreads();
    }
    if (t == 0)
        g_bias[j] = -0.5f * (D_LOG_2PI + shd[0] + shc[0]) + g_logw[j];
}

// ---------------- main GEMM (mma.sync bf16x3) ----------------
__global__ void __launch_bounds__(NTHR, 1) gemm_kernel() {
    extern __shared__ char smem[];
    uint32_t sb = smem_u32(smem);
    int tid = threadIdx.x;
    int wid = tid >> 5, lane = tid & 31;
    int rowBase = blockIdx.y * BM;
    int colBase = blockIdx.x * BN;
    float* bias_sm = (float*)smem;

    if (tid < 128) bias_sm[tid] = g_bias[colBase + tid];

    // warp tile: 16 warps = 4(m) x 4(n); warp tile 64m x 32n
    int wm = (wid & 3) * 64;
    int wn = (wid >> 2) * 32;
    int lrow = lane & 15;
    int lcol = (lane >> 4) * 16;

    // ---- precomputed cp.async offsets ----
    uint32_t gAo[4], sAo[4], gBo[2], sBo[2];
    #pragma unroll
    for (int it = 0; it < 4; it++) {
        int idx = tid + it * NTHR;          // 0..2047
        int row = idx >> 3, ch = idx & 7;
        gAo[it] = (uint32_t)((rowBase + row) * K2 + ch * 8);
        sAo[it] = swz((uint32_t)(row * 128 + ch * 16));
    }
    #pragma unroll
    for (int it = 0; it < 2; it++) {
        int idx = tid + it * NTHR;          // 0..1023
        int row = idx >> 3, ch = idx & 7;
        gBo[it] = (uint32_t)((colBase + row) * K2 + ch * 8);
        sBo[it] = swz((uint32_t)(row * 128 + ch * 16));
    }

    // ---- ldmatrix base addresses (swizzle folded; addr = base ^ kb) ----
    uint32_t baseA[4], baseB[2];
    #pragma unroll
    for (int mi = 0; mi < 4; mi++) {
        int r = wm + mi * 16 + lrow;
        baseA[mi] = sb + 512 + (uint32_t)(r * 128 + ((r & 7) << 4));
    }
    #pragma unroll
    for (int nj = 0; nj < 2; nj++) {
        int r = wn + nj * 16 + lrow;
        baseB[nj] = sb + 512 + 65536 + (uint32_t)(r * 128 + ((r & 7) << 4));
    }

    float acc[64];
    #pragma unroll
    for (int i = 0; i < 64; i++) acc[i] = 0.f;

    auto load_stage = [&](int buf, int k0) {
        uint32_t st = sb + 512 + buf * STAGE_BYTES;
        #pragma unroll
        for (int it = 0; it < 4; it++) {
            cp16(st + sAo[it],         g_Ah + gAo[it] + k0);
            cp16(st + 32768 + sAo[it], g_Al + gAo[it] + k0);
        }
        #pragma unroll
        for (int it = 0; it < 2; it++) {
            cp16(st + 65536 + sBo[it], g_Bh + gBo[it] + k0);
            cp16(st + 81920 + sBo[it], g_Bl + gBo[it] + k0);
        }
    };

    load_stage(0, 0);
    asm volatile("cp.async.commit_group;" ::: "memory");

    for (int s = 0; s < NSTEPS; s++) {
        int buf = s & 1;
        uint32_t bo = (uint32_t)buf * STAGE_BYTES;

        asm volatile("cp.async.wait_group 0;" ::: "memory");
        __syncthreads();

        if (s + 1 < NSTEPS) {
            load_stage(buf ^ 1, (s + 1) * BK);
            asm volatile("cp.async.commit_group;" ::: "memory");
        }

        #pragma unroll
        for (int ks = 0; ks < 4; ks++) {
            uint32_t kb = (uint32_t)(ks * 32 + lcol);

            // B fragments for this k-slice: 16 regs, live across the mi loop
            uint32_t bh0[4], bh1[4], bl0[4], bl1[4];
            ldsm4(bh0, (baseB[0] + bo) ^ kb);
            ldsm4(bh1, (baseB[1] + bo) ^ kb);
            ldsm4(bl0, (baseB[0] + bo + 16384u) ^ kb);
            ldsm4(bl1, (baseB[1] + bo + 16384u) ^ kb);

            // stream A fragments per mi: only 8 A-frag regs live at a time
            #pragma unroll
            for (int mi = 0; mi < 4; mi++) {
                float* C = &acc[mi * 16];
                uint32_t ah[4], al[4];
                ldsm4(ah, (baseA[mi] + bo) ^ kb);
                // Ah * Bh
                mma4(C + 0,  ah, bh0[0], bh0[2]);
                mma4(C + 4,  ah, bh0[1], bh0[3]);
                mma4(C + 8,  ah, bh1[0], bh1[2]);
                mma4(C + 12, ah, bh1[1], bh1[3]);
                // load Al while Ah*Bl issues
                ldsm4(al, (baseA[mi] + bo + 32768u) ^ kb);
                // Ah * Bl
                mma4(C + 0,  ah, bl0[0], bl0[2]);
                mma4(C + 4,  ah, bl0[1], bl0[3]);
                mma4(C + 8,  ah, bl1[0], bl1[2]);
                mma4(C + 12, ah, bl1[1], bl1[3]);
                // Al * Bh
                mma4(C + 0,  al, bh0[0], bh0[2]);
                mma4(C + 4,  al, bh0[1], bh0[3]);
                mma4(C + 8,  al, bh1[0], bh1[2]);
                mma4(C + 12, al, bh1[1], bh1[3]);
            }
        }
    }
    __syncthreads();    // all ldsm done before reusing smem as C staging

    // ---- epilogue: stage C to smem, fused lse over K=16 ----
    float* csh = (float*)(smem + 512);
    #pragma unroll
    for (int mi = 0; mi < 4; mi++)
        #pragma unroll
        for (int nj = 0; nj < 4; nj++) {
            float* a = &acc[(mi * 4 + nj) * 4];
            int r0 = wm + mi * 16 + (lane >> 2);
            int c0 = wn + nj * 8 + 2 * (lane & 3);
            csh[r0 * CPAD + c0]           = a[0];
            csh[r0 * CPAD + c0 + 1]       = a[1];
            csh[(r0 + 8) * CPAD + c0]     = a[2];
            csh[(r0 + 8) * CPAD + c0 + 1] = a[3];
        }
    __syncthreads();

    #pragma unroll
    for (int i = 0; i < 4; i++) {
        int p = tid + i * NTHR;      // 0..2047: 256 rows x 8 classes
        int row = p >> 3, cl = p & 7;
        const float* base = &csh[row * CPAD + cl * 16];
        float4 x0 = *(const float4*)(base + 0);
        float4 x1 = *(const float4*)(base + 4);
        float4 x2 = *(const float4*)(base + 8);
        float4 x3 = *(const float4*)(base + 12);
        float v[16] = {x0.x, x0.y, x0.z, x0.w, x1.x, x1.y, x1.z, x1.w,
                       x2.x, x2.y, x2.z, x2.w, x3.x, x3.y, x3.z, x3.w};
        #pragma unroll
        for (int j = 0; j < 16; j++)
            v[j] = fmaf(-0.5f, v[j], bias_sm[cl * 16 + j]);
        float m = v[0];
        #pragma unroll
        for (int j = 1; j < 16; j++) m = fmaxf(m, v[j]);
        float sum = 0.f;
        #pragma unroll
        for (int j = 0; j < 16; j++) sum += __expf(v[j] - m);
        g_cls[(size_t)(rowBase + row) * NC + (colBase >> 4) + cl] = m + __logf(sum);
    }
}

// ---------------- per-row reduction over classes ----------------
__global__ void reduce_kernel(float* __restrict__ out) {
    __shared__ float sh[256];
    size_t row = blockIdx.x;
    int t = threadIdx.x;
    float lc = -1e30f;
    if (t < NC) lc = g_cls[row * NC + t] + g_logp[t];
    sh[t] = lc;
    __syncthreads();
    for (int s = 128; s > 0; s >>= 1) { if (t < s) sh[t] = fmaxf(sh[t], sh[t + s]); __syncthreads(); }
    float M = sh[0];
    __syncthreads();
    sh[t] = (t < NC) ? __expf(lc - M) : 0.f;
    __syncthreads();
    for (int s = 128; s > 0; s >>= 1) { if (t < s) sh[t] += sh[t + s]; __syncthreads(); }
    float lse = M + __logf(sh[0]);
    if (t < NC) out[row * NC + t] = lc - lse;
}

// ---------------- launch ----------------
extern "C" void kernel_launch(void* const* d_in, const int* in_sizes, int n_in,
                              void* d_out, int out_size) {
    const float* x       = (const float*)d_in[0];
    const float* means   = (const float*)d_in[1];
    const float* bw      = (const float*)d_in[2];
    const float* weights = (const float*)d_in[3];
    const float* priors  = (const float*)d_in[4];
    float* out = (float*)d_out;

    cudaFuncSetAttribute(gemm_kernel, cudaFuncAttributeMaxDynamicSharedMemorySize, SMEM_TOTAL);

    prep_x_kernel<<<(NB * ND + 255) / 256, 256>>>(x);
    prep_wp_kernel<<<1, 256>>>(weights, priors);
    prep_comp_kernel<<<NCK, 128>>>(means, bw);

    dim3 grid(NCK / BN, NB / BM);   // (25, 32)
    gemm_kernel<<<grid, NTHR, SMEM_TOTAL>>>();

    reduce_kernel<<<NB, 256>>>(out);
}

// round 6
// speedup vs baseline: 1.0489x; 1.0489x over previous
#include <cuda_runtime.h>
#include <cuda_bf16.h>
#include <math.h>
#include <stdint.h>

// Problem constants
#define NB   8192
#define NC   200
#define NK   16
#define ND   512
#define NCK  3200
#define K2   1024          // 2*ND concatenated GEMM K
#define D_LOG_2PI 940.9930579935848f

// GEMM tiling
#define BM 128
#define BN 128
#define BK 32              // K elems per stage; hi/lo packed in one 128B row
#define NSTEPS (K2/BK)     // 32
#define NTHR 256
#define NSTAGE 3

// SMEM: [0:512) bias; stages at 512 + st*32768: A tile 16K (128 rows x [hi64B|lo64B]),
//       B tile 16K at +16384. Epilogue reuses stage area as C staging.
#define STAGE_BYTES 32768
#define SMEM_TOTAL  (512 + NSTAGE * STAGE_BYTES)
#define CPAD 136

// ---------------- scratch (device globals) ----------------
__device__ __nv_bfloat16 g_Ah[NB * K2];
__device__ __nv_bfloat16 g_Al[NB * K2];
__device__ __nv_bfloat16 g_Bh[NCK * K2];
__device__ __nv_bfloat16 g_Bl[NCK * K2];
__device__ float g_bias[NCK];
__device__ float g_logw[NCK];
__device__ float g_logp[NC];
__device__ float g_cls[NB * NC];

// ---------------- helpers ----------------
__device__ __forceinline__ uint32_t smem_u32(const void* p) {
    uint32_t a;
    asm("{ .reg .u64 t; cvta.to.shared.u64 t, %1; cvt.u32.u64 %0, t; }" : "=r"(a) : "l"(p));
    return a;
}
__device__ __forceinline__ uint32_t swz(uint32_t o) {   // SW128 over 128B rows
    return o ^ (((o >> 7) & 7) << 4);
}
__device__ __forceinline__ void cp16(uint32_t saddr, const void* gaddr) {
    asm volatile("cp.async.cg.shared.global [%0], [%1], 16;" :: "r"(saddr), "l"(gaddr));
}
__device__ __forceinline__ void ldsm4(uint32_t* r, uint32_t addr) {
    asm volatile("ldmatrix.sync.aligned.m8n8.x4.shared.b16 {%0,%1,%2,%3}, [%4];"
        : "=r"(r[0]), "=r"(r[1]), "=r"(r[2]), "=r"(r[3]) : "r"(addr));
}
__device__ __forceinline__ void mma4(float* c, const uint32_t* a, uint32_t b0, uint32_t b1) {
    asm("mma.sync.aligned.m16n8k16.row.col.f32.bf16.bf16.f32 "
        "{%0,%1,%2,%3}, {%4,%5,%6,%7}, {%8,%9}, {%0,%1,%2,%3};"
        : "+f"(c[0]), "+f"(c[1]), "+f"(c[2]), "+f"(c[3])
        : "r"(a[0]), "r"(a[1]), "r"(a[2]), "r"(a[3]), "r"(b0), "r"(b1));
}

// ---------------- prep kernels ----------------
__global__ void prep_x_kernel(const float* __restrict__ x) {
    int i = blockIdx.x * blockDim.x + threadIdx.x;
    if (i < NB * ND) {
        int b = i >> 9, d = i & 511;
        float v = x[i];
        float a = v * v;
        __nv_bfloat16 h = __float2bfloat16(a);
        g_Ah[b * K2 + d] = h;
        g_Al[b * K2 + d] = __float2bfloat16(a - __bfloat162float(h));
        __nv_bfloat16 h2 = __float2bfloat16(v);
        g_Ah[b * K2 + ND + d] = h2;
        g_Al[b * K2 + ND + d] = __float2bfloat16(v - __bfloat162float(h2));
    }
}

__global__ void prep_wp_kernel(const float* __restrict__ weights,
                               const float* __restrict__ priors) {
    __shared__ float sh[256];
    int t = threadIdx.x;
    if (t < NC) {
        float wv[NK];
        float m = -1e30f;
        #pragma unroll
        for (int k = 0; k < NK; k++) { wv[k] = weights[t * NK + k]; m = fmaxf(m, wv[k]); }
        float s = 0.f;
        #pragma unroll
        for (int k = 0; k < NK; k++) s += expf(wv[k] - m);
        float inv_s = 1.f / s;
        #pragma unroll
        for (int k = 0; k < NK; k++)
            g_logw[t * NK + k] = logf(expf(wv[k] - m) * inv_s + 1e-6f);
    }
    float pv = (t < NC) ? priors[t] : -1e30f;
    sh[t] = pv;
    __syncthreads();
    for (int s = 128; s > 0; s >>= 1) { if (t < s) sh[t] = fmaxf(sh[t], sh[t + s]); __syncthreads(); }
    float M = sh[0];
    __syncthreads();
    float e = (t < NC) ? expf(pv - M) : 0.f;
    sh[t] = e;
    __syncthreads();
    for (int s = 128; s > 0; s >>= 1) { if (t < s) sh[t] += sh[t + s]; __syncthreads(); }
    float S = sh[0];
    if (t < NC) g_logp[t] = logf(e / S + 1e-6f);
}

__global__ void prep_comp_kernel(const float* __restrict__ means,
                                 const float* __restrict__ bw) {
    int j = blockIdx.x;
    int t = threadIdx.x;   // 128
    float ld = 0.f, cj = 0.f;
    #pragma unroll
    for (int d = t; d < ND; d += 128) {
        float bv = bw[j * ND + d];
        bv = fminf(fmaxf(bv, 1e-6f), 1000.f);
        float inv = 1.0f / bv;
        float mu  = means[j * ND + d];
        float m2  = -2.0f * mu * inv;
        __nv_bfloat16 h = __float2bfloat16(inv);
        g_Bh[j * K2 + d] = h;
        g_Bl[j * K2 + d] = __float2bfloat16(inv - __bfloat162float(h));
        __nv_bfloat16 h2 = __float2bfloat16(m2);
        g_Bh[j * K2 + ND + d] = h2;
        g_Bl[j * K2 + ND + d] = __float2bfloat16(m2 - __bfloat162float(h2));
        ld += logf(bv);
        cj += mu * mu * inv;
    }
    __shared__ float shd[128], shc[128];
    shd[t] = ld; shc[t] = cj;
    __syncthreads();
    for (int s = 64; s > 0; s >>= 1) {
        if (t < s) { shd[t] += shd[t + s]; shc[t] += shc[t + s]; }
        __syncthreads();
    }
    if (t == 0)
        g_bias[j] = -0.5f * (D_LOG_2PI + shd[0] + shc[0]) + g_logw[j];
}

// ---------------- main GEMM (mma.sync bf16x3, 2 CTAs/SM) ----------------
__global__ void __launch_bounds__(NTHR, 2) gemm_kernel() {
    extern __shared__ char smem[];
    uint32_t sb = smem_u32(smem);
    int tid = threadIdx.x;
    int wid = tid >> 5, lane = tid & 31;
    int rowBase = blockIdx.y * BM;
    int colBase = blockIdx.x * BN;
    float* bias_sm = (float*)smem;

    if (tid < 128) bias_sm[tid] = g_bias[colBase + tid];

    // 8 warps = 2(m) x 4(n); warp tile 64m x 32n
    int wm = (wid & 1) * 64;
    int wn = (wid >> 1) * 32;
    int lrow = lane & 15;
    uint32_t lcol = (uint32_t)((lane >> 4) * 16);

    // ---- per-thread cp.async source pointers + smem offsets ----
    // A: 1024 cp16/stage (128 rows x 8 chunks: ch<4 = hi, ch>=4 = lo)
    const __nv_bfloat16* pA[4]; uint32_t sA[4];
    const __nv_bfloat16* pB[4]; uint32_t sB[4];
    #pragma unroll
    for (int it = 0; it < 4; it++) {
        int idx = tid + it * NTHR;             // 0..1023
        int row = idx >> 3, ch = idx & 7;
        uint32_t goff = (uint32_t)((rowBase + row) * K2 + (ch & 3) * 8);
        pA[it] = (ch < 4 ? g_Ah : g_Al) + goff;
        sA[it] = swz((uint32_t)(row * 128 + ch * 16));
        uint32_t goffB = (uint32_t)((colBase + row) * K2 + (ch & 3) * 8);
        pB[it] = (ch < 4 ? g_Bh : g_Bl) + goffB;
        sB[it] = swz((uint32_t)(row * 128 + ch * 16));
    }

    // ---- ldmatrix base addresses (col swizzle folded; addr = base ^ colbytes) ----
    uint32_t baseA[4], baseB[2];
    #pragma unroll
    for (int mi = 0; mi < 4; mi++) {
        int r = wm + mi * 16 + lrow;
        baseA[mi] = sb + 512 + (uint32_t)(r * 128 + ((r & 7) << 4));
    }
    #pragma unroll
    for (int nj = 0; nj < 2; nj++) {
        int r = wn + nj * 16 + lrow;
        baseB[nj] = sb + 512 + 16384 + (uint32_t)(r * 128 + ((r & 7) << 4));
    }

    float acc[64];
    #pragma unroll
    for (int i = 0; i < 64; i++) acc[i] = 0.f;

    auto load_stage = [&](int st, int k0) {
        uint32_t sa = sb + 512 + st * STAGE_BYTES;
        #pragma unroll
        for (int it = 0; it < 4; it++) {
            cp16(sa + sA[it],          pA[it] + k0);
            cp16(sa + 16384 + sB[it],  pB[it] + k0);
        }
        asm volatile("cp.async.commit_group;" ::: "memory");
    };

    load_stage(0, 0);
    load_stage(1, BK);

    int st = 0;
    for (int s = 0; s < NSTEPS; s++) {
        if (s < NSTEPS - 2)
            asm volatile("cp.async.wait_group 1;" ::: "memory");
        else
            asm volatile("cp.async.wait_group 0;" ::: "memory");
        __syncthreads();

        uint32_t so = (uint32_t)st * STAGE_BYTES;

        if (s + 2 < NSTEPS) {
            int nst = st + 2; if (nst >= NSTAGE) nst -= NSTAGE;
            load_stage(nst, (s + 2) * BK);
        }

        #pragma unroll
        for (int ks = 0; ks < 2; ks++) {
            uint32_t kb = (uint32_t)(ks * 32) + lcol;   // hi cols
            uint32_t kl = kb + 64u;                     // lo cols

            uint32_t bh0[4], bh1[4], bl0[4], bl1[4];
            ldsm4(bh0, (baseB[0] + so) ^ kb);
            ldsm4(bh1, (baseB[1] + so) ^ kb);
            ldsm4(bl0, (baseB[0] + so) ^ kl);
            ldsm4(bl1, (baseB[1] + so) ^ kl);

            #pragma unroll
            for (int mi = 0; mi < 4; mi++) {
                float* C = &acc[mi * 16];
                uint32_t ah[4], al[4];
                ldsm4(ah, (baseA[mi] + so) ^ kb);
                mma4(C + 0,  ah, bh0[0], bh0[2]);
                mma4(C + 4,  ah, bh0[1], bh0[3]);
                mma4(C + 8,  ah, bh1[0], bh1[2]);
                mma4(C + 12, ah, bh1[1], bh1[3]);
                ldsm4(al, (baseA[mi] + so) ^ kl);
                mma4(C + 0,  ah, bl0[0], bl0[2]);
                mma4(C + 4,  ah, bl0[1], bl0[3]);
                mma4(C + 8,  ah, bl1[0], bl1[2]);
                mma4(C + 12, ah, bl1[1], bl1[3]);
                mma4(C + 0,  al, bh0[0], bh0[2]);
                mma4(C + 4,  al, bh0[1], bh0[3]);
                mma4(C + 8,  al, bh1[0], bh1[2]);
                mma4(C + 12, al, bh1[1], bh1[3]);
            }
        }
        st++; if (st >= NSTAGE) st = 0;
    }
    __syncthreads();    // all ldsm done before reusing smem as C staging

    // ---- epilogue: stage C to smem, fused lse over K=16 ----
    float* csh = (float*)(smem + 512);
    #pragma unroll
    for (int mi = 0; mi < 4; mi++)
        #pragma unroll
        for (int nj = 0; nj < 4; nj++) {
            float* a = &acc[(mi * 4 + nj) * 4];
            int r0 = wm + mi * 16 + (lane >> 2);
            int c0 = wn + nj * 8 + 2 * (lane & 3);
            csh[r0 * CPAD + c0]           = a[0];
            csh[r0 * CPAD + c0 + 1]       = a[1];
            csh[(r0 + 8) * CPAD + c0]     = a[2];
            csh[(r0 + 8) * CPAD + c0 + 1] = a[3];
        }
    __syncthreads();

    #pragma unroll
    for (int i = 0; i < 4; i++) {
        int p = tid + i * NTHR;      // 0..1023: 128 rows x 8 classes
        int row = p >> 3, cl = p & 7;
        const float* base = &csh[row * CPAD + cl * 16];
        float4 x0 = *(const float4*)(base + 0);
        float4 x1 = *(const float4*)(base + 4);
        float4 x2 = *(const float4*)(base + 8);
        float4 x3 = *(const float4*)(base + 12);
        float v[16] = {x0.x, x0.y, x0.z, x0.w, x1.x, x1.y, x1.z, x1.w,
                       x2.x, x2.y, x2.z, x2.w, x3.x, x3.y, x3.z, x3.w};
        #pragma unroll
        for (int j = 0; j < 16; j++)
            v[j] = fmaf(-0.5f, v[j], bias_sm[cl * 16 + j]);
        float m = v[0];
        #pragma unroll
        for (int j = 1; j < 16; j++) m = fmaxf(m, v[j]);
        float sum = 0.f;
        #pragma unroll
        for (int j = 0; j < 16; j++) sum += __expf(v[j] - m);
        g_cls[(size_t)(rowBase + row) * NC + (colBase >> 4) + cl] = m + __logf(sum);
    }
}

// ---------------- per-row reduction over classes ----------------
__global__ void reduce_kernel(float* __restrict__ out) {
    __shared__ float sh[256];
    size_t row = blockIdx.x;
    int t = threadIdx.x;
    float lc = -1e30f;
    if (t < NC) lc = g_cls[row * NC + t] + g_logp[t];
    sh[t] = lc;
    __syncthreads();
    for (int s = 128; s > 0; s >>= 1) { if (t < s) sh[t] = fmaxf(sh[t], sh[t + s]); __syncthreads(); }
    float M = sh[0];
    __syncthreads();
    sh[t] = (t < NC) ? __expf(lc - M) : 0.f;
    __syncthreads();
    for (int s = 128; s > 0; s >>= 1) { if (t < s) sh[t] += sh[t + s]; __syncthreads(); }
    float lse = M + __logf(sh[0]);
    if (t < NC) out[row * NC + t] = lc - lse;
}

// ---------------- launch ----------------
extern "C" void kernel_launch(void* const* d_in, const int* in_sizes, int n_in,
                              void* d_out, int out_size) {
    const float* x       = (const float*)d_in[0];
    const float* means   = (const float*)d_in[1];
    const float* bw      = (const float*)d_in[2];
    const float* weights = (const float*)d_in[3];
    const float* priors  = (const float*)d_in[4];
    float* out = (float*)d_out;

    cudaFuncSetAttribute(gemm_kernel, cudaFuncAttributeMaxDynamicSharedMemorySize, SMEM_TOTAL);

    prep_x_kernel<<<(NB * ND + 255) / 256, 256>>>(x);
    prep_wp_kernel<<<1, 256>>>(weights, priors);
    prep_comp_kernel<<<NCK, 128>>>(means, bw);

    dim3 grid(NCK / BN, NB / BM);   // (25, 64)
    gemm_kernel<<<grid, NTHR, SMEM_TOTAL>>>();

    reduce_kernel<<<NB, 256>>>(out);
}